// round 1
// baseline (speedup 1.0000x reference)
#include <cuda_runtime.h>
#include <math.h>

// ---------------- problem constants ----------------
static constexpr int NTOK = 2048;   // tokens (2*1024)
static constexpr int Dm   = 1024;   // d_model
static constexpr int NEXP = 12;     // routed experts
static constexpr int HSh  = 2048;   // shared hidden
static constexpr int HRt  = 3072;   // routed hidden
static constexpr float TAU = 1.5f;

// ---------------- device scratch (no allocation allowed) ----------------
__device__ int   g_cnt[NEXP];
__device__ int   g_off[NEXP];
__device__ int   g_bucket[NEXP * NTOK];
__device__ float g_bw[NEXP * NTOK];
__device__ float g_hs[(size_t)NTOK * 2 * HSh];      // shared GEMM1 out  [2048, 4096]
__device__ float g_as[(size_t)NTOK * HSh];          // shared GEGLU out  [2048, 2048]
__device__ float g_hr[(size_t)2 * NTOK * 2 * HRt];  // routed GEMM1 out  [4096, 6144]
__device__ float g_ar[(size_t)2 * NTOK * HRt];      // routed GEGLU out  [4096, 3072]

// ---------------- tiny kernels ----------------
__global__ void zero_k() {
    if (threadIdx.x < NEXP) g_cnt[threadIdx.x] = 0;
}

__global__ void prefix_k() {
    if (threadIdx.x == 0) {
        int s = 0;
        for (int e = 0; e < NEXP; e++) { g_off[e] = s; s += g_cnt[e]; }
    }
}

// Router: logits = (x @ Wr + br)/TAU, top-2, softmax, bucket append.
__global__ void router_k(const float* __restrict__ x,
                         const float* __restrict__ Wr,
                         const float* __restrict__ br) {
    int n   = blockIdx.x;
    int tid = threadIdx.x;                 // 128 threads
    __shared__ float red[128 * NEXP];
    __shared__ float lg[NEXP];

    float part[NEXP];
#pragma unroll
    for (int e = 0; e < NEXP; e++) part[e] = 0.f;

    const float* xr = x + (size_t)n * Dm;
    for (int d = tid; d < Dm; d += 128) {
        float xv = xr[d];
        const float* wr = Wr + (size_t)d * NEXP;
#pragma unroll
        for (int e = 0; e < NEXP; e++) part[e] += xv * wr[e];
    }
#pragma unroll
    for (int e = 0; e < NEXP; e++) red[tid * NEXP + e] = part[e];
    __syncthreads();

    if (tid < NEXP) {
        float s = 0.f;
        for (int i = 0; i < 128; i++) s += red[i * NEXP + tid];
        lg[tid] = (s + br[tid]) / TAU;
    }
    __syncthreads();

    if (tid == 0) {
        // top-2 (strict > keeps lowest index on ties, matching jax top_k)
        int i0 = 0; float v0 = lg[0];
#pragma unroll
        for (int e = 1; e < NEXP; e++) if (lg[e] > v0) { v0 = lg[e]; i0 = e; }
        int i1 = -1; float v1 = -3.4e38f;
#pragma unroll
        for (int e = 0; e < NEXP; e++) if (e != i0 && lg[e] > v1) { v1 = lg[e]; i1 = e; }
        float e1 = __expf(v1 - v0);
        float inv = 1.f / (1.f + e1);
        float w0 = inv, w1 = e1 * inv;
        int s0 = atomicAdd(&g_cnt[i0], 1);
        g_bucket[i0 * NTOK + s0] = n;  g_bw[i0 * NTOK + s0] = w0;
        int s1 = atomicAdd(&g_cnt[i1], 1);
        g_bucket[i1 * NTOK + s1] = n;  g_bw[i1 * NTOK + s1] = w1;
    }
}

// GEGLU: act[r,c] = h[r,c] * gelu_exact(h[r,H+c])
__global__ void geglu_k(const float* __restrict__ h, float* __restrict__ act,
                        int rows, int H) {
    int i = blockIdx.x * 256 + threadIdx.x;
    if (i >= rows * H) return;
    int r = i / H, c = i - r * H;
    const float* hr = h + (size_t)r * 2 * H;
    float a = hr[c], g = hr[H + c];
    act[i] = a * (0.5f * g * (1.0f + erff(g * 0.70710678118654752f)));
}

// ---------------- tiled SGEMM ----------------
// MODE 0: C[M,N] = A@B + bias          (plain, M multiple of 128)
// MODE 1: routed GEMM1: A rows gathered via bucket (expert=blockIdx.z),
//         B/bias offset per expert, C row = off[e]+m
// MODE 2: routed GEMM2: A rows = g_ar[off[e]+m], epilogue scatter:
//         atomicAdd(out[token, c], w * (acc + bias))
static constexpr int BM = 128, BN = 128, BK = 8, TM = 8, TN = 8;

template <int MODE>
__global__ void __launch_bounds__(256)
sgemm_k(const float* __restrict__ A, const float* __restrict__ B,
        const float* __restrict__ bias, float* __restrict__ C,
        int M, int Ncol, int K) {
    int e = 0, Me = M, offE = 0;
    const int* bucket = nullptr;
    if constexpr (MODE != 0) {
        e  = blockIdx.z;
        Me = g_cnt[e];
        if ((int)blockIdx.y * BM >= Me) return;
        bucket = &g_bucket[e * NTOK];
        offE   = g_off[e];
    }

    const float* Bblk    = B;
    const float* biasblk = bias;
    if constexpr (MODE != 0) {
        Bblk    = B    + (size_t)e * K * Ncol;
        biasblk = bias + (size_t)e * Ncol;
    }

    int tid  = threadIdx.x;            // 256
    int arow = tid >> 1;               // 0..127
    int akc  = (tid & 1) << 2;         // 0 or 4
    int bkr  = tid >> 5;               // 0..7
    int bnc  = (tid & 31) << 2;        // 0..124
    int row0 = blockIdx.y * BM;
    int col0 = blockIdx.x * BN;

    int  gm     = row0 + arow;
    bool avalid = true;
    const float* Aptr = nullptr;
    if constexpr (MODE == 1) {
        avalid = (gm < Me);
        if (avalid) Aptr = A + (size_t)bucket[gm] * K + akc;
    } else if constexpr (MODE == 2) {
        avalid = (gm < Me);
        if (avalid) Aptr = A + (size_t)(offE + gm) * K + akc;
    } else {
        Aptr = A + (size_t)gm * K + akc;
    }
    const float* Bptr = Bblk + (size_t)bkr * Ncol + col0 + bnc;

    __shared__ float As[BK][BM];
    __shared__ float Bs[BK][BN];

    float acc[TM][TN];
#pragma unroll
    for (int i = 0; i < TM; i++)
#pragma unroll
        for (int j = 0; j < TN; j++) acc[i][j] = 0.f;

    int tm0 = (tid >> 4) << 3;
    int tn0 = (tid & 15) << 3;

    for (int k0 = 0; k0 < K; k0 += BK) {
        float4 av = avalid ? *(const float4*)(Aptr + k0)
                           : make_float4(0.f, 0.f, 0.f, 0.f);
        float4 bv = *(const float4*)(Bptr + (size_t)k0 * Ncol);
        As[akc + 0][arow] = av.x;
        As[akc + 1][arow] = av.y;
        As[akc + 2][arow] = av.z;
        As[akc + 3][arow] = av.w;
        *(float4*)&Bs[bkr][bnc] = bv;
        __syncthreads();
#pragma unroll
        for (int kk = 0; kk < BK; kk++) {
            float ar[TM], br[TN];
            *(float4*)&ar[0] = *(const float4*)&As[kk][tm0];
            *(float4*)&ar[4] = *(const float4*)&As[kk][tm0 + 4];
            *(float4*)&br[0] = *(const float4*)&Bs[kk][tn0];
            *(float4*)&br[4] = *(const float4*)&Bs[kk][tn0 + 4];
#pragma unroll
            for (int i = 0; i < TM; i++)
#pragma unroll
                for (int j = 0; j < TN; j++) acc[i][j] += ar[i] * br[j];
        }
        __syncthreads();
    }

    // epilogue
    float4 b0 = *(const float4*)(biasblk + col0 + tn0);
    float4 b1 = *(const float4*)(biasblk + col0 + tn0 + 4);
    float bvals[8] = {b0.x, b0.y, b0.z, b0.w, b1.x, b1.y, b1.z, b1.w};

#pragma unroll
    for (int i = 0; i < TM; i++) {
        int r = row0 + tm0 + i;
        if constexpr (MODE != 0) { if (r >= Me) break; }
        if constexpr (MODE == 2) {
            int tok = bucket[r];
            float w = g_bw[e * NTOK + r];
            float* orow = C + (size_t)tok * Ncol + col0 + tn0;
#pragma unroll
            for (int j = 0; j < TN; j++)
                atomicAdd(&orow[j], w * (acc[i][j] + bvals[j]));
        } else {
            size_t crow = (MODE == 1) ? (size_t)(offE + r) : (size_t)r;
            float* cp = C + crow * Ncol + col0 + tn0;
            float4 o0 = make_float4(acc[i][0] + bvals[0], acc[i][1] + bvals[1],
                                    acc[i][2] + bvals[2], acc[i][3] + bvals[3]);
            float4 o1 = make_float4(acc[i][4] + bvals[4], acc[i][5] + bvals[5],
                                    acc[i][6] + bvals[6], acc[i][7] + bvals[7]);
            *(float4*)cp       = o0;
            *(float4*)(cp + 4) = o1;
        }
    }
}

// ---------------- launch ----------------
extern "C" void kernel_launch(void* const* d_in, const int* in_sizes, int n_in,
                              void* d_out, int out_size) {
    const float* x   = (const float*)d_in[0];
    const float* Ws1 = (const float*)d_in[1];
    const float* bs1 = (const float*)d_in[2];
    const float* Ws2 = (const float*)d_in[3];
    const float* bs2 = (const float*)d_in[4];
    const float* We1 = (const float*)d_in[5];
    const float* be1 = (const float*)d_in[6];
    const float* We2 = (const float*)d_in[7];
    const float* be2 = (const float*)d_in[8];
    const float* Wr  = (const float*)d_in[9];
    const float* br  = (const float*)d_in[10];
    float* out = (float*)d_out;

    static float *p_hs = nullptr, *p_as = nullptr, *p_hr = nullptr, *p_ar = nullptr;
    if (!p_hs) {
        cudaGetSymbolAddress((void**)&p_hs, g_hs);
        cudaGetSymbolAddress((void**)&p_as, g_as);
        cudaGetSymbolAddress((void**)&p_hr, g_hr);
        cudaGetSymbolAddress((void**)&p_ar, g_ar);
    }

    // routing
    zero_k<<<1, 32>>>();
    router_k<<<NTOK, 128>>>(x, Wr, br);
    prefix_k<<<1, 1>>>();

    // shared expert: x[2048,1024] -> hs[2048,4096] -> as[2048,2048] -> out[2048,1024]
    sgemm_k<0><<<dim3(2 * HSh / BN, NTOK / BM), 256>>>(x, Ws1, bs1, p_hs,
                                                       NTOK, 2 * HSh, Dm);
    geglu_k<<<(NTOK * HSh + 255) / 256, 256>>>(p_hs, p_as, NTOK, HSh);
    sgemm_k<0><<<dim3(Dm / BN, NTOK / BM), 256>>>(p_as, Ws2, bs2, out,
                                                  NTOK, Dm, HSh);

    // routed experts (sparse top-2 dispatch, 4096 assignments total)
    sgemm_k<1><<<dim3(2 * HRt / BN, NTOK / BM, NEXP), 256>>>(x, We1, be1, p_hr,
                                                             0, 2 * HRt, Dm);
    geglu_k<<<(2 * NTOK * HRt + 255) / 256, 256>>>(p_hr, p_ar, 2 * NTOK, HRt);
    sgemm_k<2><<<dim3(Dm / BN, NTOK / BM, NEXP), 256>>>(p_ar, We2, be2, out,
                                                        0, Dm, HRt);
}

// round 4
// speedup vs baseline: 2.3352x; 2.3352x over previous
#include <cuda_runtime.h>
#include <cuda_bf16.h>
#include <math.h>
#include <stdint.h>

// ---------------- problem constants ----------------
static constexpr int NTOK = 2048;
static constexpr int Dm   = 1024;
static constexpr int NEXP = 12;
static constexpr int HSh  = 2048;   // shared hidden
static constexpr int HRt  = 3072;   // routed hidden
static constexpr float TAU = 1.5f;

// ---------------- device scratch (no allocation allowed) ----------------
__device__ int   g_cnt[NEXP];
__device__ int   g_off[NEXP];
__device__ int   g_bucket[NEXP * NTOK];
__device__ float g_bw[NEXP * NTOK];

__device__ float g_hs[(size_t)NTOK * 2 * HSh];       // shared GEMM1 out fp32
__device__ float g_hr[(size_t)2 * NTOK * 2 * HRt];   // routed GEMM1 out fp32

__device__ __nv_bfloat16 g_xh[(size_t)NTOK * Dm],  g_xl[(size_t)NTOK * Dm];
__device__ __nv_bfloat16 g_ash[(size_t)NTOK * HSh], g_asl[(size_t)NTOK * HSh];
__device__ __nv_bfloat16 g_arh[(size_t)2 * NTOK * HRt], g_arl[(size_t)2 * NTOK * HRt];
// transposed+split weights [N, K] bf16
__device__ __nv_bfloat16 g_w1h[(size_t)2 * HSh * Dm], g_w1l[(size_t)2 * HSh * Dm];
__device__ __nv_bfloat16 g_w2h[(size_t)Dm * HSh],     g_w2l[(size_t)Dm * HSh];
__device__ __nv_bfloat16 g_e1h[(size_t)NEXP * 2 * HRt * Dm], g_e1l[(size_t)NEXP * 2 * HRt * Dm];
__device__ __nv_bfloat16 g_e2h[(size_t)NEXP * Dm * HRt],     g_e2l[(size_t)NEXP * Dm * HRt];

// ---------------- helpers ----------------
__device__ __forceinline__ uint32_t smem_u32(const void* p) {
    uint32_t a;
    asm("{ .reg .u64 t; cvta.to.shared.u64 t, %1; cvt.u32.u64 %0, t; }" : "=r"(a) : "l"(p));
    return a;
}
__device__ __forceinline__ uint32_t swz(uint32_t b) { return b ^ ((b >> 3) & 0x70); }

__device__ __forceinline__ void cp16(uint32_t dst, const void* src, int sz) {
    asm volatile("cp.async.cg.shared.global [%0], [%1], 16, %2;"
                 :: "r"(dst), "l"(src), "r"(sz));
}
#define CP_COMMIT() asm volatile("cp.async.commit_group;" ::: "memory")

__device__ __forceinline__ void ldsm4(uint32_t* r, uint32_t addr) {
    asm volatile("ldmatrix.sync.aligned.m8n8.x4.shared.b16 {%0,%1,%2,%3}, [%4];"
                 : "=r"(r[0]), "=r"(r[1]), "=r"(r[2]), "=r"(r[3]) : "r"(addr));
}
__device__ __forceinline__ void mma16816(float* c, const uint32_t* a, const uint32_t* b) {
    asm volatile(
        "mma.sync.aligned.m16n8k16.row.col.f32.bf16.bf16.f32 "
        "{%0,%1,%2,%3}, {%4,%5,%6,%7}, {%8,%9}, {%0,%1,%2,%3};"
        : "+f"(c[0]), "+f"(c[1]), "+f"(c[2]), "+f"(c[3])
        : "r"(a[0]), "r"(a[1]), "r"(a[2]), "r"(a[3]), "r"(b[0]), "r"(b[1]));
}
__device__ __forceinline__ void split_bf16(float v, __nv_bfloat16& h, __nv_bfloat16& l) {
    h = __float2bfloat16(v);
    l = __float2bfloat16(v - __bfloat162float(h));
}

// ---------------- tiny kernels ----------------
__global__ void zero_k() { if (threadIdx.x < NEXP) g_cnt[threadIdx.x] = 0; }

__global__ void prefix_k() {
    if (threadIdx.x == 0) {
        int s = 0;
        for (int e = 0; e < NEXP; e++) { g_off[e] = s; s += g_cnt[e]; }
    }
}

__global__ void router_k(const float* __restrict__ x,
                         const float* __restrict__ Wr,
                         const float* __restrict__ br) {
    int n = blockIdx.x, tid = threadIdx.x;            // 128 threads
    __shared__ float red[128 * NEXP];
    __shared__ float lg[NEXP];
    float part[NEXP];
#pragma unroll
    for (int e = 0; e < NEXP; e++) part[e] = 0.f;
    const float* xr = x + (size_t)n * Dm;
    for (int d = tid; d < Dm; d += 128) {
        float xv = xr[d];
        const float* wr = Wr + (size_t)d * NEXP;
#pragma unroll
        for (int e = 0; e < NEXP; e++) part[e] += xv * wr[e];
    }
#pragma unroll
    for (int e = 0; e < NEXP; e++) red[tid * NEXP + e] = part[e];
    __syncthreads();
    if (tid < NEXP) {
        float s = 0.f;
        for (int i = 0; i < 128; i++) s += red[i * NEXP + tid];
        lg[tid] = (s + br[tid]) / TAU;
    }
    __syncthreads();
    if (tid == 0) {
        int i0 = 0; float v0 = lg[0];
#pragma unroll
        for (int e = 1; e < NEXP; e++) if (lg[e] > v0) { v0 = lg[e]; i0 = e; }
        int i1 = -1; float v1 = -3.4e38f;
#pragma unroll
        for (int e = 0; e < NEXP; e++) if (e != i0 && lg[e] > v1) { v1 = lg[e]; i1 = e; }
        float e1 = __expf(v1 - v0);
        float inv = 1.f / (1.f + e1);
        int s0 = atomicAdd(&g_cnt[i0], 1);
        g_bucket[i0 * NTOK + s0] = n;  g_bw[i0 * NTOK + s0] = inv;
        int s1 = atomicAdd(&g_cnt[i1], 1);
        g_bucket[i1 * NTOK + s1] = n;  g_bw[i1 * NTOK + s1] = e1 * inv;
    }
}

// elementwise split fp32 -> bf16 hi/lo
__global__ void split_k(const float* __restrict__ s, __nv_bfloat16* __restrict__ dh,
                        __nv_bfloat16* __restrict__ dl, int n) {
    int i = blockIdx.x * 256 + threadIdx.x;
    if (i >= n) return;
    __nv_bfloat16 h, l; split_bf16(s[i], h, l);
    dh[i] = h; dl[i] = l;
}

// transpose + split: src fp32 [R, C] -> dst bf16 [C, R]; z = expert slab
__global__ void tsplit_k(const float* __restrict__ src, __nv_bfloat16* __restrict__ dh,
                         __nv_bfloat16* __restrict__ dl, int R, int C) {
    __shared__ float t[32][33];
    size_t zo = (size_t)blockIdx.z * R * C;
    int c0 = blockIdx.x * 32, r0 = blockIdx.y * 32;
    int x = threadIdx.x, y = threadIdx.y;       // 32 x 8
    for (int i = y; i < 32; i += 8)
        t[i][x] = src[zo + (size_t)(r0 + i) * C + c0 + x];
    __syncthreads();
    for (int j = y; j < 32; j += 8) {
        float v = t[x][j];
        __nv_bfloat16 h, l; split_bf16(v, h, l);
        size_t o = zo + (size_t)(c0 + j) * R + r0 + x;
        dh[o] = h; dl[o] = l;
    }
}

// GEGLU + split: act = a * gelu_exact(g) -> bf16 hi/lo
__global__ void geglu_split_k(const float* __restrict__ h, __nv_bfloat16* __restrict__ oh,
                              __nv_bfloat16* __restrict__ ol, int rows, int H) {
    int i = blockIdx.x * 256 + threadIdx.x;
    if (i >= rows * H) return;
    int r = i / H, c = i - r * H;
    const float* hr = h + (size_t)r * 2 * H;
    float a = hr[c], g = hr[H + c];
    float v = a * (0.5f * g * (1.0f + erff(g * 0.70710678118654752f)));
    __nv_bfloat16 vh, vl; split_bf16(v, vh, vl);
    oh[i] = vh; ol[i] = vl;
}

// ---------------- HMMA (mma.sync) bf16x3 GEMM ----------------
// CTA 128x128, 256 threads = 8 warps (4 M x 2 N), warp tile 32x64.
// K in 64-elem SW128 chunks, cp.async double-buffered.
// MODE 0: plain C = A@B^T + bias
// MODE 1: routed GEMM1: A rows via bucket, B/bias per expert (blockIdx.z),
//         C row = off[e] + local
// MODE 2: routed GEMM2: A rows = off[e]+local, scatter atomicAdd(C[token], w*(acc+bias))
static constexpr int TILE_B = 128 * 128;                 // bytes per smem tile
static constexpr int GSMEM  = 2 * 4 * TILE_B;            // 131072

template <int MODE>
__global__ void __launch_bounds__(256, 1)
hmma_gemm(const __nv_bfloat16* __restrict__ Ah, const __nv_bfloat16* __restrict__ Al,
          const __nv_bfloat16* __restrict__ Bh, const __nv_bfloat16* __restrict__ Bl,
          const float* __restrict__ bias, float* __restrict__ C,
          int M, int N, int K) {
    extern __shared__ char sm[];
    __shared__ int   sb_tok[128];
    __shared__ float sb_w[128];

    const int tid = threadIdx.x, wid = tid >> 5, lane = tid & 31;
    const int wm = wid & 3, wn = wid >> 2;               // warp 4x2
    const int row0 = blockIdx.y * 128, col0 = blockIdx.x * 128;

    int e = 0, Me = M, offE = 0;
    if constexpr (MODE != 0) {
        e = blockIdx.z;
        Me = g_cnt[e];
        if (row0 >= Me) return;
        offE = g_off[e];
        Bh += (size_t)e * N * K;
        Bl += (size_t)e * N * K;
        bias += (size_t)e * N;
    }
    if constexpr (MODE != 0) {
        if (tid < 128) {
            int r = row0 + tid;
            sb_tok[tid] = (r < Me) ? g_bucket[e * NTOK + tid + row0] : 0;
            sb_w[tid]   = (r < Me) ? g_bw[e * NTOK + tid + row0] : 0.f;
        }
        __syncthreads();
    }

    const int nch = K >> 6;
    const uint32_t smbase = smem_u32(sm);

    auto issue_chunk = [&](int ck) {
        const int buf = ck & 1, k0 = ck << 6;
        const uint32_t base = smbase + buf * 4 * TILE_B;
#pragma unroll
        for (int s = tid; s < 4096; s += 256) {
            int t = s >> 10;            // 0:Ah 1:Al 2:Bh 3:Bl
            int slot = s & 1023;
            int r = slot >> 3, cc = slot & 7;
            uint32_t dst = base + t * TILE_B + swz((uint32_t)(r * 128 + cc * 16));
            const __nv_bfloat16* src;
            int sz = 16;
            if (t < 2) {
                const __nv_bfloat16* Ab = (t == 0) ? Ah : Al;
                size_t ro = 0;
                if constexpr (MODE == 1) {
                    if (row0 + r < Me) ro = (size_t)sb_tok[r] * K;
                    else sz = 0;
                } else if constexpr (MODE == 2) {
                    if (row0 + r < Me) ro = (size_t)(offE + row0 + r) * K;
                    else sz = 0;
                } else {
                    ro = (size_t)(row0 + r) * K;
                }
                src = Ab + ro + k0 + cc * 8;
            } else {
                const __nv_bfloat16* Bb = (t == 2) ? Bh : Bl;
                src = Bb + (size_t)(col0 + r) * K + k0 + cc * 8;
            }
            cp16(dst, src, sz);
        }
        CP_COMMIT();
    };

    float acc[2][8][4];
#pragma unroll
    for (int i = 0; i < 2; i++)
#pragma unroll
        for (int j = 0; j < 8; j++)
#pragma unroll
            for (int k = 0; k < 4; k++) acc[i][j][k] = 0.f;

    issue_chunk(0);
    for (int ck = 0; ck < nch; ck++) {
        if (ck + 1 < nch) {
            issue_chunk(ck + 1);
            asm volatile("cp.async.wait_group 1;" ::: "memory");
        } else {
            asm volatile("cp.async.wait_group 0;" ::: "memory");
        }
        __syncthreads();

        const uint32_t base = smbase + (ck & 1) * 4 * TILE_B;
        const uint32_t tAh = base, tAl = base + TILE_B;
        const uint32_t tBh = base + 2 * TILE_B, tBl = base + 3 * TILE_B;

#pragma unroll
        for (int ks = 0; ks < 4; ks++) {
            const int kb = ks * 32;      // byte offset in 128B row
            uint32_t ahf[2][4], alf[2][4];
#pragma unroll
            for (int mt = 0; mt < 2; mt++) {
                int rrow = wm * 32 + mt * 16 + (lane & 15);
                uint32_t byte = swz((uint32_t)(rrow * 128 + kb + (lane >> 4) * 16));
                ldsm4(ahf[mt], tAh + byte);
                ldsm4(alf[mt], tAl + byte);
            }
            uint32_t bhf[8][2], blf[8][2];
#pragma unroll
            for (int ng = 0; ng < 4; ng++) {
                int sub = lane >> 3;
                int nrow = wn * 64 + ng * 16 + (sub >> 1) * 8 + (lane & 7);
                uint32_t byte = swz((uint32_t)(nrow * 128 + kb + (sub & 1) * 16));
                uint32_t r4[4];
                ldsm4(r4, tBh + byte);
                bhf[2 * ng][0] = r4[0]; bhf[2 * ng][1] = r4[1];
                bhf[2 * ng + 1][0] = r4[2]; bhf[2 * ng + 1][1] = r4[3];
                ldsm4(r4, tBl + byte);
                blf[2 * ng][0] = r4[0]; blf[2 * ng][1] = r4[1];
                blf[2 * ng + 1][0] = r4[2]; blf[2 * ng + 1][1] = r4[3];
            }
#pragma unroll
            for (int mt = 0; mt < 2; mt++)
#pragma unroll
                for (int nf = 0; nf < 8; nf++) {
                    mma16816(acc[mt][nf], ahf[mt], bhf[nf]);
                    mma16816(acc[mt][nf], ahf[mt], blf[nf]);
                    mma16816(acc[mt][nf], alf[mt], bhf[nf]);
                }
        }
        __syncthreads();
    }

    // ---------------- epilogue ----------------
#pragma unroll
    for (int mt = 0; mt < 2; mt++) {
#pragma unroll
        for (int half = 0; half < 2; half++) {       // c0c1 vs c2c3 (row, row+8)
            int ml = wm * 32 + mt * 16 + (lane >> 2) + half * 8;
            if constexpr (MODE != 0) { if (row0 + ml >= Me) continue; }
#pragma unroll
            for (int nf = 0; nf < 8; nf++) {
                int colb = col0 + wn * 64 + nf * 8 + (lane & 3) * 2;
                float v0 = acc[mt][nf][half * 2 + 0] + __ldg(bias + colb + 0);
                float v1 = acc[mt][nf][half * 2 + 1] + __ldg(bias + colb + 1);
                if constexpr (MODE == 2) {
                    int tok = sb_tok[ml];
                    float w = sb_w[ml];
                    float* op = C + (size_t)tok * N + colb;
                    atomicAdd(op + 0, w * v0);
                    atomicAdd(op + 1, w * v1);
                } else {
                    size_t rr = (MODE == 1) ? (size_t)(offE + row0 + ml) : (size_t)(row0 + ml);
                    float2* cp = (float2*)(C + rr * N + colb);
                    *cp = make_float2(v0, v1);
                }
            }
        }
    }
}

// ---------------- launch ----------------
extern "C" void kernel_launch(void* const* d_in, const int* in_sizes, int n_in,
                              void* d_out, int out_size) {
    const float* x   = (const float*)d_in[0];
    const float* Ws1 = (const float*)d_in[1];
    const float* bs1 = (const float*)d_in[2];
    const float* Ws2 = (const float*)d_in[3];
    const float* bs2 = (const float*)d_in[4];
    const float* We1 = (const float*)d_in[5];
    const float* be1 = (const float*)d_in[6];
    const float* We2 = (const float*)d_in[7];
    const float* be2 = (const float*)d_in[8];
    const float* Wr  = (const float*)d_in[9];
    const float* br  = (const float*)d_in[10];
    float* out = (float*)d_out;

    cudaFuncSetAttribute(hmma_gemm<0>, cudaFuncAttributeMaxDynamicSharedMemorySize, GSMEM);
    cudaFuncSetAttribute(hmma_gemm<1>, cudaFuncAttributeMaxDynamicSharedMemorySize, GSMEM);
    cudaFuncSetAttribute(hmma_gemm<2>, cudaFuncAttributeMaxDynamicSharedMemorySize, GSMEM);

    float *p_hs, *p_hr;
    __nv_bfloat16 *p_xh, *p_xl, *p_ash, *p_asl, *p_arh, *p_arl;
    __nv_bfloat16 *p_w1h, *p_w1l, *p_w2h, *p_w2l, *p_e1h, *p_e1l, *p_e2h, *p_e2l;
    cudaGetSymbolAddress((void**)&p_hs, g_hs);
    cudaGetSymbolAddress((void**)&p_hr, g_hr);
    cudaGetSymbolAddress((void**)&p_xh, g_xh);   cudaGetSymbolAddress((void**)&p_xl, g_xl);
    cudaGetSymbolAddress((void**)&p_ash, g_ash); cudaGetSymbolAddress((void**)&p_asl, g_asl);
    cudaGetSymbolAddress((void**)&p_arh, g_arh); cudaGetSymbolAddress((void**)&p_arl, g_arl);
    cudaGetSymbolAddress((void**)&p_w1h, g_w1h); cudaGetSymbolAddress((void**)&p_w1l, g_w1l);
    cudaGetSymbolAddress((void**)&p_w2h, g_w2h); cudaGetSymbolAddress((void**)&p_w2l, g_w2l);
    cudaGetSymbolAddress((void**)&p_e1h, g_e1h); cudaGetSymbolAddress((void**)&p_e1l, g_e1l);
    cudaGetSymbolAddress((void**)&p_e2h, g_e2h); cudaGetSymbolAddress((void**)&p_e2l, g_e2l);

    // routing
    zero_k<<<1, 32>>>();
    router_k<<<NTOK, 128>>>(x, Wr, br);
    prefix_k<<<1, 1>>>();

    // operand conversion (split / transpose+split)
    split_k<<<(NTOK * Dm + 255) / 256, 256>>>(x, p_xh, p_xl, NTOK * Dm);
    tsplit_k<<<dim3(2 * HSh / 32, Dm / 32), dim3(32, 8)>>>(Ws1, p_w1h, p_w1l, Dm, 2 * HSh);
    tsplit_k<<<dim3(Dm / 32, HSh / 32), dim3(32, 8)>>>(Ws2, p_w2h, p_w2l, HSh, Dm);
    tsplit_k<<<dim3(2 * HRt / 32, Dm / 32, NEXP), dim3(32, 8)>>>(We1, p_e1h, p_e1l, Dm, 2 * HRt);
    tsplit_k<<<dim3(Dm / 32, HRt / 32, NEXP), dim3(32, 8)>>>(We2, p_e2h, p_e2l, HRt, Dm);

    // shared expert
    hmma_gemm<0><<<dim3(2 * HSh / 128, NTOK / 128), 256, GSMEM>>>(
        p_xh, p_xl, p_w1h, p_w1l, bs1, p_hs, NTOK, 2 * HSh, Dm);
    geglu_split_k<<<(NTOK * HSh + 255) / 256, 256>>>(p_hs, p_ash, p_asl, NTOK, HSh);
    hmma_gemm<0><<<dim3(Dm / 128, NTOK / 128), 256, GSMEM>>>(
        p_ash, p_asl, p_w2h, p_w2l, bs2, out, NTOK, Dm, HSh);

    // routed experts (sparse top-2)
    hmma_gemm<1><<<dim3(2 * HRt / 128, NTOK / 128, NEXP), 256, GSMEM>>>(
        p_xh, p_xl, p_e1h, p_e1l, be1, p_hr, 0, 2 * HRt, Dm);
    geglu_split_k<<<(2 * NTOK * HRt + 255) / 256, 256>>>(p_hr, p_arh, p_arl, 2 * NTOK, HRt);
    hmma_gemm<2><<<dim3(Dm / 128, NTOK / 128, NEXP), 256, GSMEM>>>(
        p_arh, p_arl, p_e2h, p_e2l, be2, out, 0, Dm, HRt);
}